// round 3
// baseline (speedup 1.0000x reference)
#include <cuda_runtime.h>
#include <stdint.h>

// Problem constants (fixed shapes for this problem)
#define BB 8
#define MM 1000000
#define NN (BB*MM)
#define GG 32                       // GRID/STRIDE = 128/4
#define NSEG (BB*GG*GG*GG)          // 262144 coarse blocks
#define PPB 4096                    // points per histogram block
#define NCHUNK ((MM + PPB - 1)/PPB) // 245

// Scratch (static device allocations only)
__device__ unsigned g_bm[NSEG];        // per-block max (ordered-uint)
__device__ unsigned g_seg[NN];         // per-point segment id
__device__ unsigned g_key[NN];         // per-point masked ordered key
__device__ unsigned g_h1[BB*2048];
__device__ unsigned g_h2[BB*2048];
__device__ unsigned g_h3[BB*1024];
__device__ unsigned g_prefix[BB];
__device__ unsigned g_krem[BB];
__device__ unsigned g_thr[BB];

// Order-preserving float <-> uint bijection (total order, strict monotone)
__device__ __forceinline__ unsigned f2o(float f){
    unsigned b = __float_as_uint(f);
    return (b & 0x80000000u) ? ~b : (b | 0x80000000u);
}
__device__ __forceinline__ float o2f(unsigned u){
    return (u & 0x80000000u) ? __uint_as_float(u ^ 0x80000000u)
                             : __uint_as_float(~u);
}

#define INF_KEY 0xFF800000u  // f2o(+inf)

// ---------------------------------------------------------------- zero scratch
__global__ void k_zero(){
    int i = blockIdx.x*blockDim.x + threadIdx.x;
    int stride = gridDim.x*blockDim.x;
    for (int j = i; j < NSEG; j += stride) g_bm[j] = 0u;
    for (int j = i; j < BB*2048; j += stride){ g_h1[j] = 0u; g_h2[j] = 0u; }
    for (int j = i; j < BB*1024; j += stride) g_h3[j] = 0u;
}

// ------------------------------------------------- pass B: seg ids + block max
__global__ void k_blockmax(const float* __restrict__ pred,
                           const int4*  __restrict__ coords){
    int i = blockIdx.x*blockDim.x + threadIdx.x;
    int stride = gridDim.x*blockDim.x;
    for (int j = i; j < NN; j += stride){
        int4 c = coords[j];   // (batch, x, y, z)
        unsigned seg = ((((unsigned)c.x * GG + ((unsigned)c.y >> 2)) * GG
                         + ((unsigned)c.z >> 2)) * GG) + ((unsigned)c.w >> 2);
        g_seg[j] = seg;
        atomicMax(&g_bm[seg], f2o(pred[j]));
    }
}

// ------------------------- pass C: masked keys + histogram of top 11 key bits
__global__ void k_key_hist(const float* __restrict__ pred){
    __shared__ unsigned sh[2048];
    for (int j = threadIdx.x; j < 2048; j += blockDim.x) sh[j] = 0u;
    __syncthreads();

    int b = blockIdx.y;
    int start = blockIdx.x * PPB;
    int cnt = min(PPB, MM - start);
    long base = (long)b * MM + start;          // divisible by 4
    const uint4*  s4 = (const uint4*)g_seg + (base >> 2);
    const float4* p4 = (const float4*)pred + (base >> 2);
    uint4*        k4 = (uint4*)g_key + (base >> 2);
    int nv = cnt >> 2;

    for (int v = threadIdx.x; v < nv; v += blockDim.x){
        uint4 s = s4[v];
        float4 p = p4[v];
        uint4 kk;
        kk.x = (p.x != o2f(g_bm[s.x])) ? f2o(p.x) : INF_KEY;
        kk.y = (p.y != o2f(g_bm[s.y])) ? f2o(p.y) : INF_KEY;
        kk.z = (p.z != o2f(g_bm[s.z])) ? f2o(p.z) : INF_KEY;
        kk.w = (p.w != o2f(g_bm[s.w])) ? f2o(p.w) : INF_KEY;
        k4[v] = kk;
        atomicAdd(&sh[kk.x >> 21], 1u);
        atomicAdd(&sh[kk.y >> 21], 1u);
        atomicAdd(&sh[kk.z >> 21], 1u);
        atomicAdd(&sh[kk.w >> 21], 1u);
    }
    __syncthreads();
    unsigned* gh = g_h1 + b*2048;
    for (int j = threadIdx.x; j < 2048; j += blockDim.x){
        unsigned c = sh[j];
        if (c) atomicAdd(&gh[j], c);
    }
}

// --------------------------------- pass P2: histogram bits [20:10] within bin1
__global__ void k_hist2(){
    __shared__ unsigned sh[2048];
    for (int j = threadIdx.x; j < 2048; j += blockDim.x) sh[j] = 0u;
    __syncthreads();

    int b = blockIdx.y;
    unsigned p = g_prefix[b];                  // 11-bit prefix
    int start = blockIdx.x * PPB;
    int cnt = min(PPB, MM - start);
    long base = (long)b * MM + start;
    const uint4* k4 = (const uint4*)g_key + (base >> 2);
    int nv = cnt >> 2;

    for (int v = threadIdx.x; v < nv; v += blockDim.x){
        uint4 kk = k4[v];
        if ((kk.x >> 21) == p) atomicAdd(&sh[(kk.x >> 10) & 2047u], 1u);
        if ((kk.y >> 21) == p) atomicAdd(&sh[(kk.y >> 10) & 2047u], 1u);
        if ((kk.z >> 21) == p) atomicAdd(&sh[(kk.z >> 10) & 2047u], 1u);
        if ((kk.w >> 21) == p) atomicAdd(&sh[(kk.w >> 10) & 2047u], 1u);
    }
    __syncthreads();
    unsigned* gh = g_h2 + b*2048;
    for (int j = threadIdx.x; j < 2048; j += blockDim.x){
        unsigned c = sh[j];
        if (c) atomicAdd(&gh[j], c);
    }
}

// ------------------------------------ pass P3: histogram bits [9:0] within bin2
__global__ void k_hist3(){
    __shared__ unsigned sh[1024];
    for (int j = threadIdx.x; j < 1024; j += blockDim.x) sh[j] = 0u;
    __syncthreads();

    int b = blockIdx.y;
    unsigned p = g_prefix[b];                  // 22-bit prefix
    int start = blockIdx.x * PPB;
    int cnt = min(PPB, MM - start);
    long base = (long)b * MM + start;
    const uint4* k4 = (const uint4*)g_key + (base >> 2);
    int nv = cnt >> 2;

    for (int v = threadIdx.x; v < nv; v += blockDim.x){
        uint4 kk = k4[v];
        if ((kk.x >> 10) == p) atomicAdd(&sh[kk.x & 1023u], 1u);
        if ((kk.y >> 10) == p) atomicAdd(&sh[kk.y & 1023u], 1u);
        if ((kk.z >> 10) == p) atomicAdd(&sh[kk.z & 1023u], 1u);
        if ((kk.w >> 10) == p) atomicAdd(&sh[kk.w & 1023u], 1u);
    }
    __syncthreads();
    unsigned* gh = g_h3 + b*1024;
    for (int j = threadIdx.x; j < 1024; j += blockDim.x){
        unsigned c = sh[j];
        if (c) atomicAdd(&gh[j], c);
    }
}

// ------------------------------ scan kernel: find bin containing kth smallest
// pass: 1 -> g_h1 (2048 bins, init krem), 2 -> g_h2 (2048), 3 -> g_h3 (1024, final)
__global__ void k_scan(int pass, const int* __restrict__ tnum){
    int b = blockIdx.x;
    const unsigned* h;
    int NB, shift, first, last;
    if (pass == 1){ h = g_h1 + b*2048; NB = 2048; shift = 0;  first = 1; last = 0; }
    else if (pass == 2){ h = g_h2 + b*2048; NB = 2048; shift = 11; first = 0; last = 0; }
    else { h = g_h3 + b*1024; NB = 1024; shift = 10; first = 0; last = 1; }

    __shared__ unsigned partial[256];
    __shared__ unsigned excl[256];
    int per = NB / 256;
    unsigned s = 0;
    for (int j = 0; j < per; j++) s += h[threadIdx.x*per + j];
    partial[threadIdx.x] = s;
    __syncthreads();
    if (threadIdx.x == 0){
        unsigned c = 0;
        for (int t = 0; t < 256; t++){ unsigned v = partial[t]; excl[t] = c; c += v; }
    }
    __syncthreads();

    unsigned krem = first ? (unsigned)(MM - tnum[0]) : g_krem[b];
    unsigned cum = excl[threadIdx.x];
    for (int j = 0; j < per; j++){
        unsigned bin = threadIdx.x*per + j;
        unsigned c = h[bin];
        if (cum < krem && cum + c >= krem){
            unsigned pref = first ? bin : ((g_prefix[b] << shift) | bin);
            if (last) g_thr[b] = pref;          // exact kth-smallest key
            else { g_prefix[b] = pref; g_krem[b] = krem - cum; }
        }
        cum += c;
    }
}

// -------------------------------------------------------- final masked output
__global__ void k_out(const float* __restrict__ pred, float* __restrict__ out){
    int v = blockIdx.x*blockDim.x + threadIdx.x;   // vector index, NN/4 total
    if (v >= NN/4) return;
    int b = v / (MM/4);
    unsigned thr = g_thr[b];
    uint4 kk = ((const uint4*)g_key)[v];
    float4 p = ((const float4*)pred)[v];
    float4 o;
    o.x = (kk.x > thr) ? p.x : 0.0f;
    o.y = (kk.y > thr) ? p.y : 0.0f;
    o.z = (kk.z > thr) ? p.z : 0.0f;
    o.w = (kk.w > thr) ? p.w : 0.0f;
    ((float4*)out)[v] = o;
}

extern "C" void kernel_launch(void* const* d_in, const int* in_sizes, int n_in,
                              void* d_out, int out_size){
    const float* pred   = (const float*)d_in[0];
    const int4*  coords = (const int4*)d_in[1];
    const int*   tnum   = (const int*)d_in[2];
    float* out = (float*)d_out;

    k_zero<<<1024, 256>>>();
    k_blockmax<<<(NN + 511)/512, 256>>>(pred, coords);

    dim3 gh(NCHUNK, BB);
    k_key_hist<<<gh, 256>>>(pred);
    k_scan<<<BB, 256>>>(1, tnum);
    k_hist2<<<gh, 256>>>();
    k_scan<<<BB, 256>>>(2, tnum);
    k_hist3<<<gh, 256>>>();
    k_scan<<<BB, 256>>>(3, tnum);

    k_out<<<(NN/4 + 255)/256, 256>>>(pred, out);
}